// round 3
// baseline (speedup 1.0000x reference)
#include <cuda_runtime.h>
#include <cstdint>

// Problem constants
#define Bsz 32
#define Ssz 512
#define Lsz 8
#define Hsz 1024
#define Dsz 64

// Scratch
__device__ float g_E[Bsz * Ssz];
__device__ float g_V[Bsz * Ssz];
__device__ float2 g_W1p[(Hsz / 2) * Dsz];   // [k2][d] -> (W1[2k2][d], W1[2k2+1][d])

#define FMA_F32X2(acc, a, b) \
    asm("fma.rn.f32x2 %0, %1, %2, %0;" : "+l"(acc) : "l"(a), "l"(b))

// ---------------- Kernel 0: pair-pack W1 along K ----------------
__global__ __launch_bounds__(256) void prep_w1(const float* __restrict__ W1) {
    int idx = blockIdx.x * 256 + threadIdx.x;       // 32768 = (H/2)*D
    if (idx >= (Hsz / 2) * Dsz) return;
    int k2 = idx >> 6, d = idx & 63;
    g_W1p[idx] = make_float2(W1[(size_t)(2 * k2) * Dsz + d],
                             W1[(size_t)(2 * k2 + 1) * Dsz + d]);
}

// ---------------- Kernel 1: token MLP GEMM with f32x2 packed FMA ----------------
#define TM 64          // tokens per block
#define KC 32          // K chunk (16 k-pairs)
#define K2C (KC / 2)
#define XR 36          // Xs row stride in floats (16B-aligned rows)

__global__ __launch_bounds__(256) void token_mlp_f32x2(
    const float* __restrict__ hidden,
    const float* __restrict__ tw,
    const float* __restrict__ b1,
    const float* __restrict__ W2,
    const float* __restrict__ b2,
    const float* __restrict__ Ws)
{
    __shared__ float  Xs[2][TM * XR];          // x = h*tw, [token][k]
    __shared__ float2 Wp_s[2][K2C * Dsz];      // [k2][d]
    __shared__ float  tws[Hsz];
    __shared__ float  wss[Hsz];

    const int tid = threadIdx.x;
    const int tx = tid & 15;        // d base
    const int ty = tid >> 4;        // token base
    const int lt = tid >> 2;        // loader token 0..63
    const int lq = tid & 3;         // loader k-quad (8 floats)

    const int b    = blockIdx.x >> 3;
    const int tok0 = (blockIdx.x & 7) * TM;

    // preload tw, Ws into smem (4 floats per thread per 1024-block)
    {
        int i = tid * 4;
        *(float4*)(&tws[i]) = *(const float4*)(tw + i);
        *(float4*)(&wss[i]) = *(const float4*)(Ws + i);
        i += 1024 - 0; // single pass: 256*4 = 1024 ✓
    }

    const float* hrow = hidden + ((size_t)(b * Ssz + tok0 + lt)) * Hsz;
    float vpart = 0.0f;

    unsigned long long acc[4][4];
    #pragma unroll
    for (int i = 0; i < 4; i++)
        #pragma unroll
        for (int j = 0; j < 4; j++) acc[i][j] = 0ull;

    __syncthreads();   // tws/wss visible

    // ---- stage chunk 0 ----
    {
        const int k0 = 0, kk = lq * 8;
        float4 h0 = *(const float4*)(hrow + k0 + kk);
        float4 h1 = *(const float4*)(hrow + k0 + kk + 4);
        float4 t0 = *(const float4*)(&tws[k0 + kk]);
        float4 t1 = *(const float4*)(&tws[k0 + kk + 4]);
        float4 s0 = *(const float4*)(&wss[k0 + kk]);
        float4 s1 = *(const float4*)(&wss[k0 + kk + 4]);
        vpart = fmaf(h0.x, s0.x, fmaf(h0.y, s0.y, fmaf(h0.z, s0.z, fmaf(h0.w, s0.w, vpart))));
        vpart = fmaf(h1.x, s1.x, fmaf(h1.y, s1.y, fmaf(h1.z, s1.z, fmaf(h1.w, s1.w, vpart))));
        *(float4*)(&Xs[0][lt * XR + kk])     = make_float4(h0.x*t0.x, h0.y*t0.y, h0.z*t0.z, h0.w*t0.w);
        *(float4*)(&Xs[0][lt * XR + kk + 4]) = make_float4(h1.x*t1.x, h1.y*t1.y, h1.z*t1.z, h1.w*t1.w);
        const uint4* wg = (const uint4*)(g_W1p) + 2 * tid;   // chunk0 rows
        uint4* wsm = (uint4*)(&Wp_s[0][0]) + 2 * tid;
        wsm[0] = wg[0];
        wsm[1] = wg[1];
    }
    __syncthreads();

    const int NCHUNK = Hsz / KC;   // 32
    for (int c = 0; c < NCHUNK; c++) {
        const int buf = c & 1;
        // ---- prefetch-stage chunk c+1 into other buffer ----
        if (c + 1 < NCHUNK) {
            const int nb = 1 - buf;
            const int k0 = (c + 1) * KC, kk = lq * 8;
            float4 h0 = *(const float4*)(hrow + k0 + kk);
            float4 h1 = *(const float4*)(hrow + k0 + kk + 4);
            float4 t0 = *(const float4*)(&tws[k0 + kk]);
            float4 t1 = *(const float4*)(&tws[k0 + kk + 4]);
            float4 s0 = *(const float4*)(&wss[k0 + kk]);
            float4 s1 = *(const float4*)(&wss[k0 + kk + 4]);
            vpart = fmaf(h0.x, s0.x, fmaf(h0.y, s0.y, fmaf(h0.z, s0.z, fmaf(h0.w, s0.w, vpart))));
            vpart = fmaf(h1.x, s1.x, fmaf(h1.y, s1.y, fmaf(h1.z, s1.z, fmaf(h1.w, s1.w, vpart))));
            *(float4*)(&Xs[nb][lt * XR + kk])     = make_float4(h0.x*t0.x, h0.y*t0.y, h0.z*t0.z, h0.w*t0.w);
            *(float4*)(&Xs[nb][lt * XR + kk + 4]) = make_float4(h1.x*t1.x, h1.y*t1.y, h1.z*t1.z, h1.w*t1.w);
            const uint4* wg = (const uint4*)(g_W1p + (size_t)(c + 1) * K2C * Dsz) + 2 * tid;
            uint4* wsm = (uint4*)(&Wp_s[nb][0]) + 2 * tid;
            wsm[0] = wg[0];
            wsm[1] = wg[1];
        }

        // ---- compute chunk c ----
        #pragma unroll
        for (int k2 = 0; k2 < K2C; k2++) {
            unsigned long long x0 = *(const unsigned long long*)(&Xs[buf][(ty +  0) * XR + 2 * k2]);
            unsigned long long x1 = *(const unsigned long long*)(&Xs[buf][(ty + 16) * XR + 2 * k2]);
            unsigned long long x2 = *(const unsigned long long*)(&Xs[buf][(ty + 32) * XR + 2 * k2]);
            unsigned long long x3 = *(const unsigned long long*)(&Xs[buf][(ty + 48) * XR + 2 * k2]);
            unsigned long long w0 = *(const unsigned long long*)(&Wp_s[buf][k2 * Dsz + tx +  0]);
            unsigned long long w1 = *(const unsigned long long*)(&Wp_s[buf][k2 * Dsz + tx + 16]);
            unsigned long long w2 = *(const unsigned long long*)(&Wp_s[buf][k2 * Dsz + tx + 32]);
            unsigned long long w3 = *(const unsigned long long*)(&Wp_s[buf][k2 * Dsz + tx + 48]);
            FMA_F32X2(acc[0][0], x0, w0); FMA_F32X2(acc[0][1], x0, w1);
            FMA_F32X2(acc[0][2], x0, w2); FMA_F32X2(acc[0][3], x0, w3);
            FMA_F32X2(acc[1][0], x1, w0); FMA_F32X2(acc[1][1], x1, w1);
            FMA_F32X2(acc[1][2], x1, w2); FMA_F32X2(acc[1][3], x1, w3);
            FMA_F32X2(acc[2][0], x2, w0); FMA_F32X2(acc[2][1], x2, w1);
            FMA_F32X2(acc[2][2], x2, w2); FMA_F32X2(acc[2][3], x2, w3);
            FMA_F32X2(acc[3][0], x3, w0); FMA_F32X2(acc[3][1], x3, w1);
            FMA_F32X2(acc[3][2], x3, w2); FMA_F32X2(acc[3][3], x3, w3);
        }
        __syncthreads();
    }

    // ---- V: reduce over the 4 loader quads of each token ----
    vpart += __shfl_xor_sync(0xffffffffu, vpart, 1, 4);
    vpart += __shfl_xor_sync(0xffffffffu, vpart, 2, 4);
    if (lq == 0) g_V[b * Ssz + tok0 + lt] = vpart;

    // ---- E epilogue: relu(acc + b1) . W2, reduce across 16 tx lanes ----
    const float b2v = b2[0];
    #pragma unroll
    for (int ti = 0; ti < 4; ti++) {
        float e = 0.0f;
        #pragma unroll
        for (int di = 0; di < 4; di++) {
            int d = tx + 16 * di;
            unsigned long long a = acc[ti][di];
            float lo = __uint_as_float((uint32_t)a);
            float hi = __uint_as_float((uint32_t)(a >> 32));
            float val = lo + hi;
            e = fmaf(fmaxf(val + b1[d], 0.0f), W2[d], e);
        }
        e += __shfl_xor_sync(0xffffffffu, e, 1, 16);
        e += __shfl_xor_sync(0xffffffffu, e, 2, 16);
        e += __shfl_xor_sync(0xffffffffu, e, 4, 16);
        e += __shfl_xor_sync(0xffffffffu, e, 8, 16);
        if (tx == 0) g_E[b * Ssz + tok0 + ty + 16 * ti] = e + b2v;
    }
}

// ---------------- Kernel 2: spans ----------------
__global__ __launch_bounds__(256) void span_kernel(
    const int* __restrict__ seqlen,
    const float* __restrict__ bs,
    float* __restrict__ out)
{
    int idx = blockIdx.x * blockDim.x + threadIdx.x;
    if (idx >= Bsz * Ssz) return;
    int b = idx >> 9;
    int s = idx & (Ssz - 1);
    int len = seqlen[b];

    float ev[Lsz], vv[Lsz];
    #pragma unroll
    for (int j = 0; j < Lsz; j++) {
        int p = min(s + j, Ssz - 1);
        ev[j] = g_E[(b << 9) + p];
        vv[j] = g_V[(b << 9) + p];
    }
    const bool span_valid = (s < len);
    const float bsv = bs[0];

    float M = -1e30f, sum = 0.0f, wsum = 0.0f;
    #pragma unroll
    for (int l = 0; l < Lsz; l++) {
        if (s + l < len) {
            float e = ev[l];
            float newM = fmaxf(M, e);
            float scale = expf(M - newM);
            float p = expf(e - newM);
            sum  = sum  * scale + p;
            wsum = wsum * scale + p * vv[l];
            M = newM;
        }
        float score = (sum > 0.0f) ? (wsum / sum + bsv) : bsv;
        out[(size_t)idx * Lsz + l] = span_valid ? score : 0.0f;
    }
}

extern "C" void kernel_launch(void* const* d_in, const int* in_sizes, int n_in,
                              void* d_out, int out_size)
{
    const float* hidden = (const float*)d_in[0];
    const int*   seqlen = (const int*)  d_in[1];
    const float* tw     = (const float*)d_in[2];
    const float* W1     = (const float*)d_in[3];
    const float* b1     = (const float*)d_in[4];
    const float* W2     = (const float*)d_in[5];
    const float* b2     = (const float*)d_in[6];
    const float* Ws     = (const float*)d_in[7];
    const float* bs     = (const float*)d_in[8];
    float* out = (float*)d_out;

    prep_w1<<<128, 256>>>(W1);
    token_mlp_f32x2<<<(Bsz * Ssz) / TM, 256>>>(hidden, tw, b1, W2, b2, Ws);
    span_kernel<<<(Bsz * Ssz) / 256, 256>>>(seqlen, bs, out);
}

// round 4
// speedup vs baseline: 1.0527x; 1.0527x over previous
#include <cuda_runtime.h>
#include <cstdint>

// Problem constants
#define Bsz 32
#define Ssz 512
#define Lsz 8
#define Hsz 1024
#define Dsz 64

// Scratch
__device__ float g_E[Bsz * Ssz];
__device__ float g_V[Bsz * Ssz];
__device__ float2 g_W1p[(Hsz / 2) * Dsz];   // [k2][d] -> (W1[2k2][d], W1[2k2+1][d])

typedef unsigned long long u64;

#define FMA_F32X2(acc, a, b) \
    asm("fma.rn.f32x2 %0, %1, %2, %0;" : "+l"(acc) : "l"(a), "l"(b))

// ---------------- Kernel 0: pair-pack W1 along K ----------------
__global__ __launch_bounds__(256) void prep_w1(const float* __restrict__ W1) {
    int idx = blockIdx.x * 256 + threadIdx.x;       // 32768 = (H/2)*D
    if (idx >= (Hsz / 2) * Dsz) return;
    int k2 = idx >> 6, d = idx & 63;
    g_W1p[idx] = make_float2(W1[(size_t)(2 * k2) * Dsz + d],
                             W1[(size_t)(2 * k2 + 1) * Dsz + d]);
}

// ---------------- Kernel 1: token MLP GEMM, f32x2, 128x64 tile ----------------
#define TM 128          // tokens per block
#define KC 32           // K floats per chunk (16 k-pairs)
#define K2C (KC / 2)
#define XR 36           // Xs row stride in floats
#define XS_FLOATS (TM * XR)               // 4608 per buffer
#define WP_F2 (K2C * Dsz)                 // 1024 float2 per buffer
#define SMEM_BYTES (2 * XS_FLOATS * 4 + 2 * WP_F2 * 8)   // 36864 + 16384 = 53248

__global__ __launch_bounds__(256, 1) void token_mlp_f32x2(
    const float* __restrict__ hidden,
    const float* __restrict__ tw,
    const float* __restrict__ b1,
    const float* __restrict__ W2,
    const float* __restrict__ b2,
    const float* __restrict__ Ws)
{
    extern __shared__ char smem[];
    float*  Xs = (float*)smem;                          // [2][TM][XR]
    float2* Wp = (float2*)(smem + 2 * XS_FLOATS * 4);   // [2][K2C*Dsz]

    const int tid = threadIdx.x;
    const int tx = tid & 15;        // d group: d in {tx, tx+16, tx+32, tx+48}
    const int ty = tid >> 4;        // token group: {ty + 16i}, i<8
    const int lt = tid >> 1;        // loader token 0..127
    const int lq = tid & 1;         // loader half (16 floats)

    const int gtok0 = blockIdx.x * TM;
    const float* hrow = hidden + (size_t)(gtok0 + lt) * Hsz;

    float vpart = 0.0f;
    u64 acc[8][4];
    #pragma unroll
    for (int i = 0; i < 8; i++)
        #pragma unroll
        for (int j = 0; j < 4; j++) acc[i][j] = 0ull;

    // ---- stage chunk 0 ----
    {
        const int kk = lq * 16;
        float* xrow = Xs + lt * XR;
        #pragma unroll
        for (int q = 0; q < 4; q++) {
            float4 h = *(const float4*)(hrow + kk + q * 4);
            float4 t = *(const float4*)(tw + kk + q * 4);
            float4 s = *(const float4*)(Ws + kk + q * 4);
            vpart = fmaf(h.x, s.x, fmaf(h.y, s.y, fmaf(h.z, s.z, fmaf(h.w, s.w, vpart))));
            *(float4*)(xrow + kk + q * 4) = make_float4(h.x*t.x, h.y*t.y, h.z*t.z, h.w*t.w);
        }
        const uint4* wg = (const uint4*)g_W1p;
        uint4* ws = (uint4*)Wp;
        ws[tid] = wg[tid];
        ws[tid + 256] = wg[tid + 256];
    }
    __syncthreads();

    const int NCHUNK = Hsz / KC;   // 32
    for (int c = 0; c < NCHUNK; c++) {
        const int buf = c & 1;

        // ---- prefetch-stage chunk c+1 ----
        if (c + 1 < NCHUNK) {
            const int nb = 1 - buf;
            const int k0 = (c + 1) * KC, kk = lq * 16;
            float* xrow = Xs + nb * XS_FLOATS + lt * XR;
            #pragma unroll
            for (int q = 0; q < 4; q++) {
                float4 h = *(const float4*)(hrow + k0 + kk + q * 4);
                float4 t = *(const float4*)(tw + k0 + kk + q * 4);
                float4 s = *(const float4*)(Ws + k0 + kk + q * 4);
                vpart = fmaf(h.x, s.x, fmaf(h.y, s.y, fmaf(h.z, s.z, fmaf(h.w, s.w, vpart))));
                *(float4*)(xrow + kk + q * 4) = make_float4(h.x*t.x, h.y*t.y, h.z*t.z, h.w*t.w);
            }
            const uint4* wg = (const uint4*)(g_W1p + (size_t)(c + 1) * WP_F2);
            uint4* ws = (uint4*)(Wp + nb * WP_F2);
            ws[tid] = wg[tid];
            ws[tid + 256] = wg[tid + 256];
        }

        // ---- compute chunk c ----
        const float*  XsB = Xs + buf * XS_FLOATS;
        const float2* WpB = Wp + buf * WP_F2;
        #pragma unroll
        for (int k2 = 0; k2 < K2C; k2++) {
            u64 w0 = *(const u64*)(WpB + k2 * Dsz + tx +  0);
            u64 w1 = *(const u64*)(WpB + k2 * Dsz + tx + 16);
            u64 w2 = *(const u64*)(WpB + k2 * Dsz + tx + 32);
            u64 w3 = *(const u64*)(WpB + k2 * Dsz + tx + 48);
            #pragma unroll
            for (int i = 0; i < 8; i++) {
                u64 x = *(const u64*)(XsB + (ty + 16 * i) * XR + 2 * k2);
                FMA_F32X2(acc[i][0], x, w0);
                FMA_F32X2(acc[i][1], x, w1);
                FMA_F32X2(acc[i][2], x, w2);
                FMA_F32X2(acc[i][3], x, w3);
            }
        }
        __syncthreads();
    }

    // ---- V: reduce over the 2 loader halves of each token ----
    vpart += __shfl_xor_sync(0xffffffffu, vpart, 1, 2);
    if (lq == 0) g_V[gtok0 + lt] = vpart;

    // ---- E epilogue: relu(acc + b1) . W2, reduce across 16 tx lanes ----
    const float b2v = b2[0];
    float b1r[4], w2r[4];
    #pragma unroll
    for (int j = 0; j < 4; j++) {
        b1r[j] = b1[tx + 16 * j];
        w2r[j] = W2[tx + 16 * j];
    }
    #pragma unroll
    for (int i = 0; i < 8; i++) {
        float e = 0.0f;
        #pragma unroll
        for (int j = 0; j < 4; j++) {
            u64 a = acc[i][j];
            float lo = __uint_as_float((uint32_t)a);
            float hi = __uint_as_float((uint32_t)(a >> 32));
            e = fmaf(fmaxf(lo + hi + b1r[j], 0.0f), w2r[j], e);
        }
        e += __shfl_xor_sync(0xffffffffu, e, 1, 16);
        e += __shfl_xor_sync(0xffffffffu, e, 2, 16);
        e += __shfl_xor_sync(0xffffffffu, e, 4, 16);
        e += __shfl_xor_sync(0xffffffffu, e, 8, 16);
        if (tx == 0) g_E[gtok0 + ty + 16 * i] = e + b2v;
    }
}

// ---------------- Kernel 2: spans, E/V tiled through smem ----------------
__global__ __launch_bounds__(256) void span_kernel(
    const int* __restrict__ seqlen,
    const float* __restrict__ bs,
    float* __restrict__ out)
{
    __shared__ float Es[256 + Lsz];
    __shared__ float Vs[256 + Lsz];

    const int tid = threadIdx.x;
    const int idx0 = blockIdx.x * 256;          // block covers idx0..idx0+255 (same b)
    const int b = idx0 >> 9;
    const int s0 = idx0 & (Ssz - 1);
    const int len = seqlen[b];

    // load E/V tile (clamped at sentence-buffer end)
    for (int i = tid; i < 256 + Lsz; i += 256) {
        int p = min(s0 + i, Ssz - 1);
        Es[i] = g_E[(b << 9) + p];
        Vs[i] = g_V[(b << 9) + p];
    }
    __syncthreads();

    const int s = s0 + tid;
    const bool span_valid = (s < len);
    const float bsv = bs[0];

    float M = -1e30f, sum = 0.0f, wsum = 0.0f;
    #pragma unroll
    for (int l = 0; l < Lsz; l++) {
        if (s + l < len) {
            float e = Es[tid + l];
            float newM = fmaxf(M, e);
            float scale = expf(M - newM);
            float p = expf(e - newM);
            sum  = sum  * scale + p;
            wsum = wsum * scale + p * Vs[tid + l];
            M = newM;
        }
        float score = (sum > 0.0f) ? (wsum / sum + bsv) : bsv;
        out[(size_t)(idx0 + tid) * Lsz + l] = span_valid ? score : 0.0f;
    }
}

extern "C" void kernel_launch(void* const* d_in, const int* in_sizes, int n_in,
                              void* d_out, int out_size)
{
    const float* hidden = (const float*)d_in[0];
    const int*   seqlen = (const int*)  d_in[1];
    const float* tw     = (const float*)d_in[2];
    const float* W1     = (const float*)d_in[3];
    const float* b1     = (const float*)d_in[4];
    const float* W2     = (const float*)d_in[5];
    const float* b2     = (const float*)d_in[6];
    const float* Ws     = (const float*)d_in[7];
    const float* bs     = (const float*)d_in[8];
    float* out = (float*)d_out;

    static bool attr_set = false;
    if (!attr_set) {
        cudaFuncSetAttribute(token_mlp_f32x2,
                             cudaFuncAttributeMaxDynamicSharedMemorySize, SMEM_BYTES);
        attr_set = true;
    }

    prep_w1<<<128, 256>>>(W1);
    token_mlp_f32x2<<<(Bsz * Ssz) / TM, 256, SMEM_BYTES>>>(hidden, tw, b1, W2, b2, Ws);
    span_kernel<<<(Bsz * Ssz) / 256, 256>>>(seqlen, bs, out);
}

// round 5
// speedup vs baseline: 1.2835x; 1.2192x over previous
#include <cuda_runtime.h>
#include <cuda_bf16.h>
#include <cstdint>

// Problem constants
#define Bsz 32
#define Ssz 512
#define Lsz 8
#define Hsz 1024
#define Dsz 64

typedef uint32_t u32;

// Scratch
__device__ float g_E[Bsz * Ssz];
__device__ float g_V[Bsz * Ssz];
__device__ __nv_bfloat16 g_Wh[Dsz * Hsz];   // [d][k] hi
__device__ __nv_bfloat16 g_Wl[Dsz * Hsz];   // [d][k] lo

// ---------------- PTX wrappers (base ISA, sm_80+) ----------------
__device__ __forceinline__ u32 smem_u32(const void* p) {
    u32 a;
    asm("{ .reg .u64 t; cvta.to.shared.u64 t, %1; cvt.u32.u64 %0, t; }" : "=r"(a) : "l"(p));
    return a;
}
__device__ __forceinline__ void ldsm4(u32* r, u32 addr) {
    asm volatile("ldmatrix.sync.aligned.m8n8.x4.shared.b16 {%0,%1,%2,%3}, [%4];"
                 : "=r"(r[0]), "=r"(r[1]), "=r"(r[2]), "=r"(r[3]) : "r"(addr));
}
__device__ __forceinline__ void mma_bf16(float* c, const u32* a, u32 b0, u32 b1) {
    asm volatile("mma.sync.aligned.m16n8k16.row.col.f32.bf16.bf16.f32 "
                 "{%0,%1,%2,%3}, {%4,%5,%6,%7}, {%8,%9}, {%0,%1,%2,%3};"
                 : "+f"(c[0]), "+f"(c[1]), "+f"(c[2]), "+f"(c[3])
                 : "r"(a[0]), "r"(a[1]), "r"(a[2]), "r"(a[3]), "r"(b0), "r"(b1));
}

// ---------------- Kernel 0: split W1 -> bf16 hi/lo, transposed [d][k] ----------------
__global__ __launch_bounds__(256) void prep_w1(const float* __restrict__ W1) {
    int idx = blockIdx.x * 256 + threadIdx.x;   // 65536
    if (idx >= Dsz * Hsz) return;
    int d = idx >> 10, k = idx & 1023;
    float w = W1[(size_t)k * Dsz + d];
    __nv_bfloat16 hi = __float2bfloat16(w);
    float lo = w - __bfloat162float(hi);
    g_Wh[idx] = hi;
    g_Wl[idx] = __float2bfloat16(lo);
}

// ---------------- Kernel 1: token MLP via mma.sync bf16 split ----------------
#define TMB 128               // tokens per block
#define KCH 64                // K per chunk
#define NCHUNK (Hsz / KCH)    // 16
// smem layout per buffer (bytes): Xh 16K | Xl 16K | Wh 8K | Wl 8K
#define XH_OFF 0
#define XL_OFF 16384
#define WH_OFF 32768
#define WL_OFF 40960
#define BUFS   49152
#define EP_OFF (2 * BUFS)             // Epart: 8 warps x 64 tokens x f32 = 2 KB
#define SMEM_TOTAL (EP_OFF + 8 * 64 * 4)

__global__ __launch_bounds__(256, 2) void token_mlp_mma(
    const float* __restrict__ hidden,
    const float* __restrict__ tw,
    const float* __restrict__ b1,
    const float* __restrict__ W2,
    const float* __restrict__ b2,
    const float* __restrict__ Ws)
{
    extern __shared__ char smem[];
    const u32 sb = smem_u32(smem);
    float* Epart = (float*)(smem + EP_OFF);

    const int tid  = threadIdx.x;
    const int w    = tid >> 5;
    const int lane = tid & 31;
    const int mb   = (w & 3) * 16;    // d tile base
    const int th   = w >> 2;          // token half (0/1)

    const int gtok0 = blockIdx.x * TMB;

    // staging ids
    const int lt = tid >> 1;          // token row 0..127
    const int kb = (tid & 1) * 32;    // k sub-base within chunk
    const float* hrow = hidden + (size_t)(gtok0 + lt) * Hsz;

    // ldmatrix lane addressing
    const int tId = lane >> 3, lr = lane & 7;
    const u32 xorv = (u32)(lr << 4);
    const u32 aRowB = (u32)((mb + lr + ((tId & 1) << 3)) << 7);
    const u32 aColB = (u32)((tId >> 1) << 4);
    const u32 bRowB = (u32)((th * 64 + lr + ((tId >> 1) << 3)) << 7);
    const u32 bColB = (u32)((tId & 1) << 4);

    float acc[8][4];
    #pragma unroll
    for (int i = 0; i < 8; i++)
        #pragma unroll
        for (int j = 0; j < 4; j++) acc[i][j] = 0.0f;
    float vpart = 0.0f;

    // ---------- staging lambda (chunk c into buffer bi) ----------
    auto stage = [&](int c, int bi) {
        const int k0 = c * KCH;
        char* bp = smem + bi * BUFS;
        // X: this thread covers token lt, k [kb, kb+32)
        #pragma unroll
        for (int i = 0; i < 4; i++) {
            float4 a = *(const float4*)(hrow + k0 + kb + 8 * i);
            float4 bq = *(const float4*)(hrow + k0 + kb + 8 * i + 4);
            float4 ta = *(const float4*)(tw + k0 + kb + 8 * i);
            float4 tb = *(const float4*)(tw + k0 + kb + 8 * i + 4);
            float4 sa = *(const float4*)(Ws + k0 + kb + 8 * i);
            float4 sbq = *(const float4*)(Ws + k0 + kb + 8 * i + 4);
            vpart = fmaf(a.x, sa.x, fmaf(a.y, sa.y, fmaf(a.z, sa.z, fmaf(a.w, sa.w, vpart))));
            vpart = fmaf(bq.x, sbq.x, fmaf(bq.y, sbq.y, fmaf(bq.z, sbq.z, fmaf(bq.w, sbq.w, vpart))));
            float x0 = a.x * ta.x, x1 = a.y * ta.y, x2 = a.z * ta.z, x3 = a.w * ta.w;
            float x4 = bq.x * tb.x, x5 = bq.y * tb.y, x6 = bq.z * tb.z, x7 = bq.w * tb.w;
            __nv_bfloat162 h01 = __floats2bfloat162_rn(x0, x1);
            __nv_bfloat162 h23 = __floats2bfloat162_rn(x2, x3);
            __nv_bfloat162 h45 = __floats2bfloat162_rn(x4, x5);
            __nv_bfloat162 h67 = __floats2bfloat162_rn(x6, x7);
            __nv_bfloat162 l01 = __floats2bfloat162_rn(x0 - __bfloat162float(h01.x), x1 - __bfloat162float(h01.y));
            __nv_bfloat162 l23 = __floats2bfloat162_rn(x2 - __bfloat162float(h23.x), x3 - __bfloat162float(h23.y));
            __nv_bfloat162 l45 = __floats2bfloat162_rn(x4 - __bfloat162float(h45.x), x5 - __bfloat162float(h45.y));
            __nv_bfloat162 l67 = __floats2bfloat162_rn(x6 - __bfloat162float(h67.x), x7 - __bfloat162float(h67.y));
            u32 seg = (u32)(kb / 8 + i);                       // 16B segment in row
            u32 off = (u32)(lt << 7) + ((seg << 4) ^ ((u32)(lt & 7) << 4));
            *(uint4*)(bp + XH_OFF + off) = make_uint4(
                *(u32*)&h01, *(u32*)&h23, *(u32*)&h45, *(u32*)&h67);
            *(uint4*)(bp + XL_OFF + off) = make_uint4(
                *(u32*)&l01, *(u32*)&l23, *(u32*)&l45, *(u32*)&l67);
        }
        // W: 64 rows x 64 bf16 = 512 x 16B units; thread does units tid, tid+256
        #pragma unroll
        for (int r = 0; r < 2; r++) {
            int u = tid + r * 256;
            int row = u >> 3, seg = u & 7;
            u32 off = (u32)(row << 7) + ((u32)(seg << 4) ^ ((u32)(row & 7) << 4));
            *(uint4*)(bp + WH_OFF + off) = *(const uint4*)(g_Wh + row * Hsz + k0 + seg * 8);
            *(uint4*)(bp + WL_OFF + off) = *(const uint4*)(g_Wl + row * Hsz + k0 + seg * 8);
        }
    };

    stage(0, 0);
    __syncthreads();

    for (int c = 0; c < NCHUNK; c++) {
        const int bi = c & 1;
        if (c + 1 < NCHUNK) stage(c + 1, 1 - bi);

        const u32 xh = sb + bi * BUFS + XH_OFF;
        const u32 xl = sb + bi * BUFS + XL_OFF;
        const u32 wh = sb + bi * BUFS + WH_OFF;
        const u32 wl = sb + bi * BUFS + WL_OFF;

        #pragma unroll
        for (int ks = 0; ks < 4; ks++) {
            const u32 kc = (u32)(ks << 5);
            u32 ah[4], al[4];
            ldsm4(ah, wh + aRowB + ((kc + aColB) ^ xorv));
            ldsm4(al, wl + aRowB + ((kc + aColB) ^ xorv));
            #pragma unroll
            for (int jj = 0; jj < 4; jj++) {
                const u32 rofs = bRowB + (u32)(jj << 11);   // jj*16 rows *128B
                u32 bh[4], bl[4];
                ldsm4(bh, xh + rofs + ((kc + bColB) ^ xorv));
                ldsm4(bl, xl + rofs + ((kc + bColB) ^ xorv));
                mma_bf16(acc[2 * jj],     ah, bh[0], bh[1]);
                mma_bf16(acc[2 * jj],     al, bh[0], bh[1]);
                mma_bf16(acc[2 * jj],     ah, bl[0], bl[1]);
                mma_bf16(acc[2 * jj + 1], ah, bh[2], bh[3]);
                mma_bf16(acc[2 * jj + 1], al, bh[2], bh[3]);
                mma_bf16(acc[2 * jj + 1], ah, bl[2], bl[3]);
            }
        }
        __syncthreads();
    }

    // ---- V: lanes 2j,2j+1 hold halves of token lt ----
    vpart += __shfl_xor_sync(0xffffffffu, vpart, 1);
    if ((tid & 1) == 0) g_V[gtok0 + lt] = vpart;

    // ---- E partials: relu(acc + b1) . W2 over this warp's 16 d's ----
    {
        const int g = lane >> 2;
        const int d1 = mb + g, d2 = mb + 8 + g;
        const float b1a = b1[d1], b1b = b1[d2];
        const float w2a = W2[d1], w2b = W2[d2];
        #pragma unroll
        for (int j = 0; j < 8; j++) {
            float p0 = fmaxf(acc[j][0] + b1a, 0.0f) * w2a + fmaxf(acc[j][2] + b1b, 0.0f) * w2b;
            float p1 = fmaxf(acc[j][1] + b1a, 0.0f) * w2a + fmaxf(acc[j][3] + b1b, 0.0f) * w2b;
            p0 += __shfl_xor_sync(0xffffffffu, p0, 4);
            p0 += __shfl_xor_sync(0xffffffffu, p0, 8);
            p0 += __shfl_xor_sync(0xffffffffu, p0, 16);
            p1 += __shfl_xor_sync(0xffffffffu, p1, 4);
            p1 += __shfl_xor_sync(0xffffffffu, p1, 8);
            p1 += __shfl_xor_sync(0xffffffffu, p1, 16);
            if (lane < 4) {
                Epart[w * 64 + j * 8 + 2 * lane]     = p0;
                Epart[w * 64 + j * 8 + 2 * lane + 1] = p1;
            }
        }
    }
    __syncthreads();
    if (tid < TMB) {
        int thh = tid >> 6, loc = tid & 63;
        float e = Epart[(thh * 4 + 0) * 64 + loc] + Epart[(thh * 4 + 1) * 64 + loc]
                + Epart[(thh * 4 + 2) * 64 + loc] + Epart[(thh * 4 + 3) * 64 + loc];
        g_E[gtok0 + tid] = e + b2[0];
    }
}

// ---------------- Kernel 2: spans, E/V tiled through smem ----------------
__global__ __launch_bounds__(256) void span_kernel(
    const int* __restrict__ seqlen,
    const float* __restrict__ bs,
    float* __restrict__ out)
{
    __shared__ float Es[256 + Lsz];
    __shared__ float Vs[256 + Lsz];

    const int tid = threadIdx.x;
    const int idx0 = blockIdx.x * 256;
    const int b = idx0 >> 9;
    const int s0 = idx0 & (Ssz - 1);
    const int len = seqlen[b];

    for (int i = tid; i < 256 + Lsz; i += 256) {
        int p = min(s0 + i, Ssz - 1);
        Es[i] = g_E[(b << 9) + p];
        Vs[i] = g_V[(b << 9) + p];
    }
    __syncthreads();

    const int s = s0 + tid;
    const bool span_valid = (s < len);
    const float bsv = bs[0];

    float M = -1e30f, sum = 0.0f, wsum = 0.0f;
    #pragma unroll
    for (int l = 0; l < Lsz; l++) {
        if (s + l < len) {
            float e = Es[tid + l];
            float newM = fmaxf(M, e);
            float scale = expf(M - newM);
            float p = expf(e - newM);
            sum  = sum  * scale + p;
            wsum = wsum * scale + p * Vs[tid + l];
            M = newM;
        }
        float score = (sum > 0.0f) ? (wsum / sum + bsv) : bsv;
        out[(size_t)(idx0 + tid) * Lsz + l] = span_valid ? score : 0.0f;
    }
}

extern "C" void kernel_launch(void* const* d_in, const int* in_sizes, int n_in,
                              void* d_out, int out_size)
{
    const float* hidden = (const float*)d_in[0];
    const int*   seqlen = (const int*)  d_in[1];
    const float* tw     = (const float*)d_in[2];
    const float* W1     = (const float*)d_in[3];
    const float* b1     = (const float*)d_in[4];
    const float* W2     = (const float*)d_in[5];
    const float* b2     = (const float*)d_in[6];
    const float* Ws     = (const float*)d_in[7];
    const float* bs     = (const float*)d_in[8];
    float* out = (float*)d_out;

    static bool attr_set = false;
    if (!attr_set) {
        cudaFuncSetAttribute(token_mlp_mma,
                             cudaFuncAttributeMaxDynamicSharedMemorySize, SMEM_TOTAL);
        attr_set = true;
    }

    prep_w1<<<256, 256>>>(W1);
    token_mlp_mma<<<(Bsz * Ssz) / TMB, 256, SMEM_TOTAL>>>(hidden, tw, b1, W2, b2, Ws);
    span_kernel<<<(Bsz * Ssz) / 256, 256>>>(seqlen, bs, out);
}

// round 6
// speedup vs baseline: 1.7231x; 1.3425x over previous
#include <cuda_runtime.h>
#include <cuda_fp16.h>
#include <cstdint>

// Problem constants
#define Bsz 32
#define Ssz 512
#define Lsz 8
#define Hsz 1024
#define Dsz 64

typedef uint32_t u32;

// Scratch
__device__ float g_E[Bsz * Ssz];
__device__ float g_V[Bsz * Ssz];

// ---------------- PTX wrappers (base ISA, sm_80+) ----------------
__device__ __forceinline__ u32 smem_u32(const void* p) {
    u32 a;
    asm("{ .reg .u64 t; cvta.to.shared.u64 t, %1; cvt.u32.u64 %0, t; }" : "=r"(a) : "l"(p));
    return a;
}
__device__ __forceinline__ void ldsm4(u32* r, u32 addr) {
    asm volatile("ldmatrix.sync.aligned.m8n8.x4.shared.b16 {%0,%1,%2,%3}, [%4];"
                 : "=r"(r[0]), "=r"(r[1]), "=r"(r[2]), "=r"(r[3]) : "r"(addr));
}
__device__ __forceinline__ void mma_fp16(float* c, const u32* a, u32 b0, u32 b1) {
    asm volatile("mma.sync.aligned.m16n8k16.row.col.f32.f16.f16.f32 "
                 "{%0,%1,%2,%3}, {%4,%5,%6,%7}, {%8,%9}, {%0,%1,%2,%3};"
                 : "+f"(c[0]), "+f"(c[1]), "+f"(c[2]), "+f"(c[3])
                 : "r"(a[0]), "r"(a[1]), "r"(a[2]), "r"(a[3]), "r"(b0), "r"(b1));
}
__device__ __forceinline__ u32 pack_h2(float a, float b) {
    __half2 h = __floats2half2_rn(a, b);
    return *reinterpret_cast<u32*>(&h);
}

// ---------------- Kernel 1: token MLP via single fp16 mma.sync ----------------
#define TMB 128               // tokens per block
#define KCH 64                // K per chunk
#define NCHUNK (Hsz / KCH)    // 16
// per-buffer smem: X 128x128B = 16K | W 64x128B = 8K
#define XH_OFF 0
#define WH_OFF 16384
#define BUFS   24576
#define EP_OFF (2 * BUFS)
#define SMEM_TOTAL (EP_OFF + 8 * 64 * 4)   // 51200

__global__ __launch_bounds__(256, 2) void token_mlp_mma(
    const float* __restrict__ hidden,
    const float* __restrict__ tw,
    const float* __restrict__ W1,
    const float* __restrict__ b1,
    const float* __restrict__ W2,
    const float* __restrict__ b2,
    const float* __restrict__ Ws)
{
    extern __shared__ char smem[];
    const u32 sb = smem_u32(smem);
    float* Epart = (float*)(smem + EP_OFF);

    const int tid  = threadIdx.x;
    const int w    = tid >> 5;
    const int lane = tid & 31;
    const int mb   = (w & 3) * 16;    // d tile base
    const int th   = w >> 2;          // token half (0/1)

    const int gtok0 = blockIdx.x * TMB;

    // X staging ids
    const int lt = tid >> 1;          // token row 0..127
    const int kb = (tid & 1) * 32;    // k sub-base within chunk
    const float* hrow = hidden + (size_t)(gtok0 + lt) * Hsz;
    // W staging ids
    const int wd = tid & 63;          // d row
    const int wq = tid >> 6;          // k quarter (16 k's)

    // ldmatrix lane addressing (validated round 5)
    const int tId = lane >> 3, lr = lane & 7;
    const u32 xorv = (u32)(lr << 4);
    const u32 aRowB = (u32)((mb + lr + ((tId & 1) << 3)) << 7);
    const u32 aColB = (u32)((tId >> 1) << 4);
    const u32 bRowB = (u32)((th * 64 + lr + ((tId >> 1) << 3)) << 7);
    const u32 bColB = (u32)((tId & 1) << 4);

    float acc[8][4];
    #pragma unroll
    for (int i = 0; i < 8; i++)
        #pragma unroll
        for (int j = 0; j < 4; j++) acc[i][j] = 0.0f;
    float vpart = 0.0f;

    // ---------- staging: chunk c into buffer bi ----------
    auto stage = [&](int c, int bi) {
        const int k0 = c * KCH;
        char* bp = smem + bi * BUFS;
        // X: token lt, k [kb, kb+32); x = h*tw -> fp16; fuse V
        #pragma unroll
        for (int i = 0; i < 4; i++) {
            float4 a  = *(const float4*)(hrow + k0 + kb + 8 * i);
            float4 bq = *(const float4*)(hrow + k0 + kb + 8 * i + 4);
            float4 ta = *(const float4*)(tw + k0 + kb + 8 * i);
            float4 tb = *(const float4*)(tw + k0 + kb + 8 * i + 4);
            float4 sa = *(const float4*)(Ws + k0 + kb + 8 * i);
            float4 sq = *(const float4*)(Ws + k0 + kb + 8 * i + 4);
            vpart = fmaf(a.x, sa.x, fmaf(a.y, sa.y, fmaf(a.z, sa.z, fmaf(a.w, sa.w, vpart))));
            vpart = fmaf(bq.x, sq.x, fmaf(bq.y, sq.y, fmaf(bq.z, sq.z, fmaf(bq.w, sq.w, vpart))));
            u32 p0 = pack_h2(a.x * ta.x,  a.y * ta.y);
            u32 p1 = pack_h2(a.z * ta.z,  a.w * ta.w);
            u32 p2 = pack_h2(bq.x * tb.x, bq.y * tb.y);
            u32 p3 = pack_h2(bq.z * tb.z, bq.w * tb.w);
            u32 seg = (u32)(kb / 8 + i);
            u32 off = (u32)(lt << 7) + ((seg << 4) ^ ((u32)(lt & 7) << 4));
            *(uint4*)(bp + XH_OFF + off) = make_uint4(p0, p1, p2, p3);
        }
        // W: convert W1[k][d] chunk -> fp16 [d][k] swizzled.
        // thread covers d=wd, k = k0 + wq*16 + (0..15); LDGs coalesced over d.
        {
            const float* wsrc = W1 + (size_t)(k0 + wq * 16) * Dsz + wd;
            u32 hp[8];
            #pragma unroll
            for (int j = 0; j < 8; j++)
                hp[j] = pack_h2(wsrc[(2 * j) * Dsz], wsrc[(2 * j + 1) * Dsz]);
            u32 s0 = (u32)(wq * 2), s1 = s0 + 1;
            u32 rb = (u32)(wd << 7);
            u32 xw = (u32)((wd & 7) << 4);
            *(uint4*)(bp + WH_OFF + rb + ((s0 << 4) ^ xw)) = make_uint4(hp[0], hp[1], hp[2], hp[3]);
            *(uint4*)(bp + WH_OFF + rb + ((s1 << 4) ^ xw)) = make_uint4(hp[4], hp[5], hp[6], hp[7]);
        }
    };

    stage(0, 0);
    __syncthreads();

    for (int c = 0; c < NCHUNK; c++) {
        const int bi = c & 1;
        if (c + 1 < NCHUNK) stage(c + 1, 1 - bi);

        const u32 xh = sb + bi * BUFS + XH_OFF;
        const u32 wh = sb + bi * BUFS + WH_OFF;

        #pragma unroll
        for (int ks = 0; ks < 4; ks++) {
            const u32 kc = (u32)(ks << 5);
            u32 ah[4];
            ldsm4(ah, wh + aRowB + ((kc + aColB) ^ xorv));
            #pragma unroll
            for (int jj = 0; jj < 4; jj++) {
                const u32 rofs = bRowB + (u32)(jj << 11);
                u32 bh[4];
                ldsm4(bh, xh + rofs + ((kc + bColB) ^ xorv));
                mma_fp16(acc[2 * jj],     ah, bh[0], bh[1]);
                mma_fp16(acc[2 * jj + 1], ah, bh[2], bh[3]);
            }
        }
        __syncthreads();
    }

    // ---- V: lanes 2j,2j+1 hold halves of token lt ----
    vpart += __shfl_xor_sync(0xffffffffu, vpart, 1);
    if ((tid & 1) == 0) g_V[gtok0 + lt] = vpart;

    // ---- E partials: relu(acc + b1) . W2 over this warp's 16 d's ----
    {
        const int g = lane >> 2;
        const int d1 = mb + g, d2 = mb + 8 + g;
        const float b1a = b1[d1], b1b = b1[d2];
        const float w2a = W2[d1], w2b = W2[d2];
        #pragma unroll
        for (int j = 0; j < 8; j++) {
            float p0 = fmaxf(acc[j][0] + b1a, 0.0f) * w2a + fmaxf(acc[j][2] + b1b, 0.0f) * w2b;
            float p1 = fmaxf(acc[j][1] + b1a, 0.0f) * w2a + fmaxf(acc[j][3] + b1b, 0.0f) * w2b;
            p0 += __shfl_xor_sync(0xffffffffu, p0, 4);
            p0 += __shfl_xor_sync(0xffffffffu, p0, 8);
            p0 += __shfl_xor_sync(0xffffffffu, p0, 16);
            p1 += __shfl_xor_sync(0xffffffffu, p1, 4);
            p1 += __shfl_xor_sync(0xffffffffu, p1, 8);
            p1 += __shfl_xor_sync(0xffffffffu, p1, 16);
            if (lane < 4) {
                Epart[w * 64 + j * 8 + 2 * lane]     = p0;
                Epart[w * 64 + j * 8 + 2 * lane + 1] = p1;
            }
        }
    }
    __syncthreads();
    if (tid < TMB) {
        int thh = tid >> 6, loc = tid & 63;
        float e = Epart[(thh * 4 + 0) * 64 + loc] + Epart[(thh * 4 + 1) * 64 + loc]
                + Epart[(thh * 4 + 2) * 64 + loc] + Epart[(thh * 4 + 3) * 64 + loc];
        g_E[gtok0 + tid] = e + b2[0];
    }
}

// ---------------- Kernel 2: spans, E/V tiled through smem ----------------
__global__ __launch_bounds__(256) void span_kernel(
    const int* __restrict__ seqlen,
    const float* __restrict__ bs,
    float* __restrict__ out)
{
    __shared__ float Es[256 + Lsz];
    __shared__ float Vs[256 + Lsz];

    const int tid = threadIdx.x;
    const int idx0 = blockIdx.x * 256;
    const int b = idx0 >> 9;
    const int s0 = idx0 & (Ssz - 1);
    const int len = seqlen[b];

    for (int i = tid; i < 256 + Lsz; i += 256) {
        int p = min(s0 + i, Ssz - 1);
        Es[i] = g_E[(b << 9) + p];
        Vs[i] = g_V[(b << 9) + p];
    }
    __syncthreads();

    const int s = s0 + tid;
    const bool span_valid = (s < len);
    const float bsv = bs[0];

    float M = -1e30f, sum = 0.0f, wsum = 0.0f;
    #pragma unroll
    for (int l = 0; l < Lsz; l++) {
        if (s + l < len) {
            float e = Es[tid + l];
            float newM = fmaxf(M, e);
            float scale = expf(M - newM);
            float p = expf(e - newM);
            sum  = sum  * scale + p;
            wsum = wsum * scale + p * Vs[tid + l];
            M = newM;
        }
        float score = (sum > 0.0f) ? (wsum / sum + bsv) : bsv;
        out[(size_t)(idx0 + tid) * Lsz + l] = span_valid ? score : 0.0f;
    }
}

extern "C" void kernel_launch(void* const* d_in, const int* in_sizes, int n_in,
                              void* d_out, int out_size)
{
    const float* hidden = (const float*)d_in[0];
    const int*   seqlen = (const int*)  d_in[1];
    const float* tw     = (const float*)d_in[2];
    const float* W1     = (const float*)d_in[3];
    const float* b1     = (const float*)d_in[4];
    const float* W2     = (const float*)d_in[5];
    const float* b2     = (const float*)d_in[6];
    const float* Ws     = (const float*)d_in[7];
    const float* bs     = (const float*)d_in[8];
    float* out = (float*)d_out;

    static bool attr_set = false;
    if (!attr_set) {
        cudaFuncSetAttribute(token_mlp_mma,
                             cudaFuncAttributeMaxDynamicSharedMemorySize, SMEM_TOTAL);
        attr_set = true;
    }

    token_mlp_mma<<<(Bsz * Ssz) / TMB, 256, SMEM_TOTAL>>>(hidden, tw, W1, b1, W2, b2, Ws);
    span_kernel<<<(Bsz * Ssz) / 256, 256>>>(seqlen, bs, out);
}

// round 7
// speedup vs baseline: 2.0909x; 1.2135x over previous
#include <cuda_runtime.h>
#include <cuda_fp16.h>
#include <cstdint>

// Problem constants
#define Bsz 32
#define Ssz 512
#define Lsz 8
#define Hsz 1024
#define Dsz 64

typedef uint32_t u32;

// Scratch
__device__ float g_E[Bsz * Ssz];
__device__ float g_V[Bsz * Ssz];

// ---------------- PTX wrappers (base ISA, sm_80+) ----------------
__device__ __forceinline__ u32 smem_u32(const void* p) {
    u32 a;
    asm("{ .reg .u64 t; cvta.to.shared.u64 t, %1; cvt.u32.u64 %0, t; }" : "=r"(a) : "l"(p));
    return a;
}
__device__ __forceinline__ void ldsm4(u32* r, u32 addr) {
    asm volatile("ldmatrix.sync.aligned.m8n8.x4.shared.b16 {%0,%1,%2,%3}, [%4];"
                 : "=r"(r[0]), "=r"(r[1]), "=r"(r[2]), "=r"(r[3]) : "r"(addr));
}
__device__ __forceinline__ void mma_fp16(float* c, const u32* a, u32 b0, u32 b1) {
    asm volatile("mma.sync.aligned.m16n8k16.row.col.f32.f16.f16.f32 "
                 "{%0,%1,%2,%3}, {%4,%5,%6,%7}, {%8,%9}, {%0,%1,%2,%3};"
                 : "+f"(c[0]), "+f"(c[1]), "+f"(c[2]), "+f"(c[3])
                 : "r"(a[0]), "r"(a[1]), "r"(a[2]), "r"(a[3]), "r"(b0), "r"(b1));
}
__device__ __forceinline__ u32 pack_h2(float a, float b) {
    __half2 h = __floats2half2_rn(a, b);
    return *reinterpret_cast<u32*>(&h);
}

// ---------------- Kernel 1: token MLP via fp16 mma.sync, TMB=64 / occ 2 ----------------
#define TMB 64                // tokens per block
#define KCH 64                // K per chunk
#define NCHUNK (Hsz / KCH)    // 16
// per-buffer smem: X 64x128B = 8K | W 64x128B = 8K
#define XH_OFF 0
#define WH_OFF 8192
#define BUFS   16384
#define EP_OFF (2 * BUFS)
#define SMEM_TOTAL (EP_OFF + 8 * 32 * 4)   // 33792

__global__ __launch_bounds__(256, 2) void token_mlp_mma(
    const float* __restrict__ hidden,
    const float* __restrict__ tw,
    const float* __restrict__ W1,
    const float* __restrict__ b1,
    const float* __restrict__ W2,
    const float* __restrict__ b2,
    const float* __restrict__ Ws)
{
    extern __shared__ char smem[];
    const u32 sb = smem_u32(smem);
    float* Epart = (float*)(smem + EP_OFF);

    const int tid  = threadIdx.x;
    const int w    = tid >> 5;
    const int lane = tid & 31;
    const int mb   = (w & 3) * 16;    // d tile base
    const int th   = w >> 2;          // token half (0/1), 32 tokens each

    const int gtok0 = blockIdx.x * TMB;

    // X staging ids: 4 threads per token, 16 k's each
    const int lt = tid >> 2;          // token row 0..63
    const int kq = tid & 3;           // k quarter base (16 floats)
    const float* hrow = hidden + (size_t)(gtok0 + lt) * Hsz;
    // W staging ids
    const int wd = tid & 63;          // d row
    const int wq = tid >> 6;          // k quarter (16 k's)

    // ldmatrix lane addressing
    const int tId = lane >> 3, lr = lane & 7;
    const u32 xorv = (u32)(lr << 4);
    const u32 aRowB = (u32)((mb + lr + ((tId & 1) << 3)) << 7);
    const u32 aColB = (u32)((tId >> 1) << 4);
    const u32 bRowB = (u32)((th * 32 + lr + ((tId >> 1) << 3)) << 7);
    const u32 bColB = (u32)((tId & 1) << 4);

    float acc[4][4];
    #pragma unroll
    for (int i = 0; i < 4; i++)
        #pragma unroll
        for (int j = 0; j < 4; j++) acc[i][j] = 0.0f;
    float vpart = 0.0f;

    // ---------- staging: chunk c into buffer bi ----------
    auto stage = [&](int c, int bi) {
        const int k0 = c * KCH + kq * 16;
        char* bp = smem + bi * BUFS;
        // X: token lt, 16 k's; x = h*tw -> fp16; fuse V
        #pragma unroll
        for (int i = 0; i < 2; i++) {
            float4 a  = *(const float4*)(hrow + k0 + 8 * i);
            float4 bq = *(const float4*)(hrow + k0 + 8 * i + 4);
            float4 ta = *(const float4*)(tw + k0 + 8 * i);
            float4 tb = *(const float4*)(tw + k0 + 8 * i + 4);
            float4 sa = *(const float4*)(Ws + k0 + 8 * i);
            float4 sq = *(const float4*)(Ws + k0 + 8 * i + 4);
            vpart = fmaf(a.x, sa.x, fmaf(a.y, sa.y, fmaf(a.z, sa.z, fmaf(a.w, sa.w, vpart))));
            vpart = fmaf(bq.x, sq.x, fmaf(bq.y, sq.y, fmaf(bq.z, sq.z, fmaf(bq.w, sq.w, vpart))));
            u32 p0 = pack_h2(a.x * ta.x,  a.y * ta.y);
            u32 p1 = pack_h2(a.z * ta.z,  a.w * ta.w);
            u32 p2 = pack_h2(bq.x * tb.x, bq.y * tb.y);
            u32 p3 = pack_h2(bq.z * tb.z, bq.w * tb.w);
            u32 seg = (u32)(kq * 2 + i);
            u32 off = (u32)(lt << 7) + ((seg << 4) ^ ((u32)(lt & 7) << 4));
            *(uint4*)(bp + XH_OFF + off) = make_uint4(p0, p1, p2, p3);
        }
        // W: W1[k][d] chunk -> fp16 [d][k] swizzled (thread: d=wd, 16 k's)
        {
            const float* wsrc = W1 + (size_t)(c * KCH + wq * 16) * Dsz + wd;
            u32 hp[8];
            #pragma unroll
            for (int j = 0; j < 8; j++)
                hp[j] = pack_h2(wsrc[(2 * j) * Dsz], wsrc[(2 * j + 1) * Dsz]);
            u32 s0 = (u32)(wq * 2), s1 = s0 + 1;
            u32 rb = (u32)(wd << 7);
            u32 xw = (u32)((wd & 7) << 4);
            *(uint4*)(bp + WH_OFF + rb + ((s0 << 4) ^ xw)) = make_uint4(hp[0], hp[1], hp[2], hp[3]);
            *(uint4*)(bp + WH_OFF + rb + ((s1 << 4) ^ xw)) = make_uint4(hp[4], hp[5], hp[6], hp[7]);
        }
    };

    stage(0, 0);
    __syncthreads();

    for (int c = 0; c < NCHUNK; c++) {
        const int bi = c & 1;
        if (c + 1 < NCHUNK) stage(c + 1, 1 - bi);

        const u32 xh = sb + bi * BUFS + XH_OFF;
        const u32 wh = sb + bi * BUFS + WH_OFF;

        #pragma unroll
        for (int ks = 0; ks < 4; ks++) {
            const u32 kc = (u32)(ks << 5);
            u32 ah[4];
            ldsm4(ah, wh + aRowB + ((kc + aColB) ^ xorv));
            #pragma unroll
            for (int jj = 0; jj < 2; jj++) {
                const u32 rofs = bRowB + (u32)(jj << 11);
                u32 bh[4];
                ldsm4(bh, xh + rofs + ((kc + bColB) ^ xorv));
                mma_fp16(acc[2 * jj],     ah, bh[0], bh[1]);
                mma_fp16(acc[2 * jj + 1], ah, bh[2], bh[3]);
            }
        }
        __syncthreads();
    }

    // ---- V: 4 lanes per token (kq groups) ----
    vpart += __shfl_xor_sync(0xffffffffu, vpart, 1);
    vpart += __shfl_xor_sync(0xffffffffu, vpart, 2);
    if ((tid & 3) == 0) g_V[gtok0 + lt] = vpart;

    // ---- E partials: relu(acc + b1) . W2 over this warp's 16 d's ----
    {
        const int g = lane >> 2;
        const int d1 = mb + g, d2 = mb + 8 + g;
        const float b1a = b1[d1], b1b = b1[d2];
        const float w2a = W2[d1], w2b = W2[d2];
        #pragma unroll
        for (int j = 0; j < 4; j++) {
            float p0 = fmaxf(acc[j][0] + b1a, 0.0f) * w2a + fmaxf(acc[j][2] + b1b, 0.0f) * w2b;
            float p1 = fmaxf(acc[j][1] + b1a, 0.0f) * w2a + fmaxf(acc[j][3] + b1b, 0.0f) * w2b;
            p0 += __shfl_xor_sync(0xffffffffu, p0, 4);
            p0 += __shfl_xor_sync(0xffffffffu, p0, 8);
            p0 += __shfl_xor_sync(0xffffffffu, p0, 16);
            p1 += __shfl_xor_sync(0xffffffffu, p1, 4);
            p1 += __shfl_xor_sync(0xffffffffu, p1, 8);
            p1 += __shfl_xor_sync(0xffffffffu, p1, 16);
            if (lane < 4) {
                Epart[w * 32 + j * 8 + 2 * lane]     = p0;
                Epart[w * 32 + j * 8 + 2 * lane + 1] = p1;
            }
        }
    }
    __syncthreads();
    if (tid < TMB) {
        int half = tid >> 5, loc = tid & 31;
        float e = Epart[(half * 4 + 0) * 32 + loc] + Epart[(half * 4 + 1) * 32 + loc]
                + Epart[(half * 4 + 2) * 32 + loc] + Epart[(half * 4 + 3) * 32 + loc];
        g_E[gtok0 + tid] = e + b2[0];
    }
}

// ---------------- Kernel 2: spans, 128 blocks x 128 threads ----------------
#define SPT 128   // spans per block
__global__ __launch_bounds__(SPT) void span_kernel(
    const int* __restrict__ seqlen,
    const float* __restrict__ bs,
    float* __restrict__ out)
{
    __shared__ float Es[SPT + Lsz];
    __shared__ float Vs[SPT + Lsz];

    const int tid = threadIdx.x;
    const int idx0 = blockIdx.x * SPT;
    const int b = idx0 >> 9;
    const int s0 = idx0 & (Ssz - 1);
    const int len = seqlen[b];

    for (int i = tid; i < SPT + Lsz; i += SPT) {
        int p = min(s0 + i, Ssz - 1);
        Es[i] = g_E[(b << 9) + p];
        Vs[i] = g_V[(b << 9) + p];
    }
    __syncthreads();

    const int s = s0 + tid;
    const bool span_valid = (s < len);
    const float bsv = bs[0];

    float M = -1e30f, sum = 0.0f, wsum = 0.0f;
    #pragma unroll
    for (int l = 0; l < Lsz; l++) {
        if (s + l < len) {
            float e = Es[tid + l];
            float newM = fmaxf(M, e);
            float scale = expf(M - newM);
            float p = expf(e - newM);
            sum  = sum  * scale + p;
            wsum = wsum * scale + p * Vs[tid + l];
            M = newM;
        }
        float score = (sum > 0.0f) ? (wsum / sum + bsv) : bsv;
        out[(size_t)(idx0 + tid) * Lsz + l] = span_valid ? score : 0.0f;
    }
}

extern "C" void kernel_launch(void* const* d_in, const int* in_sizes, int n_in,
                              void* d_out, int out_size)
{
    const float* hidden = (const float*)d_in[0];
    const int*   seqlen = (const int*)  d_in[1];
    const float* tw     = (const float*)d_in[2];
    const float* W1     = (const float*)d_in[3];
    const float* b1     = (const float*)d_in[4];
    const float* W2     = (const float*)d_in[5];
    const float* b2     = (const float*)d_in[6];
    const float* Ws     = (const float*)d_in[7];
    const float* bs     = (const float*)d_in[8];
    float* out = (float*)d_out;

    static bool attr_set = false;
    if (!attr_set) {
        cudaFuncSetAttribute(token_mlp_mma,
                             cudaFuncAttributeMaxDynamicSharedMemorySize, SMEM_TOTAL);
        attr_set = true;
    }

    token_mlp_mma<<<(Bsz * Ssz) / TMB, 256, SMEM_TOTAL>>>(hidden, tw, W1, b1, W2, b2, Ws);
    span_kernel<<<(Bsz * Ssz) / SPT, SPT>>>(seqlen, bs, out);
}

// round 8
// speedup vs baseline: 2.4052x; 1.1503x over previous
#include <cuda_runtime.h>
#include <cuda_fp16.h>
#include <cstdint>

// Problem constants
#define Bsz 32
#define Ssz 512
#define Lsz 8
#define Hsz 1024
#define Dsz 64

typedef uint32_t u32;

// Scratch
__device__ float g_E[Bsz * Ssz];
__device__ float g_V[Bsz * Ssz];
// W' = diag(tw) @ W1, fp16, [chunk][d][k] in the exact swizzled smem image (16 x 8 KB)
__device__ __align__(16) char g_Wp[16 * 8192];

// ---------------- PTX wrappers (base ISA, sm_80+) ----------------
__device__ __forceinline__ u32 smem_u32(const void* p) {
    u32 a;
    asm("{ .reg .u64 t; cvta.to.shared.u64 t, %1; cvt.u32.u64 %0, t; }" : "=r"(a) : "l"(p));
    return a;
}
__device__ __forceinline__ void ldsm4(u32* r, u32 addr) {
    asm volatile("ldmatrix.sync.aligned.m8n8.x4.shared.b16 {%0,%1,%2,%3}, [%4];"
                 : "=r"(r[0]), "=r"(r[1]), "=r"(r[2]), "=r"(r[3]) : "r"(addr));
}
__device__ __forceinline__ void mma_fp16(float* c, const u32* a, u32 b0, u32 b1) {
    asm volatile("mma.sync.aligned.m16n8k16.row.col.f32.f16.f16.f32 "
                 "{%0,%1,%2,%3}, {%4,%5,%6,%7}, {%8,%9}, {%0,%1,%2,%3};"
                 : "+f"(c[0]), "+f"(c[1]), "+f"(c[2]), "+f"(c[3])
                 : "r"(a[0]), "r"(a[1]), "r"(a[2]), "r"(a[3]), "r"(b0), "r"(b1));
}
__device__ __forceinline__ u32 pack_h2(float a, float b) {
    __half2 h = __floats2half2_rn(a, b);
    return *reinterpret_cast<u32*>(&h);
}

// ---------------- Kernel 0: W' = tw * W1 -> fp16, pre-swizzled ----------------
// unit = 16 bytes = 8 k's of one d row. 8192 units total.
__global__ __launch_bounds__(256) void prep_wp(
    const float* __restrict__ tw, const float* __restrict__ W1)
{
    int u = blockIdx.x * 256 + threadIdx.x;     // 0..8191
    int c = u >> 9, r = u & 511;
    int d = r >> 3, s = r & 7;
    int k0 = c * 64 + s * 8;
    float4 t0 = *(const float4*)(tw + k0);
    float4 t1 = *(const float4*)(tw + k0 + 4);
    const float* wsrc = W1 + (size_t)k0 * Dsz + d;
    u32 p0 = pack_h2(t0.x * wsrc[0 * Dsz], t0.y * wsrc[1 * Dsz]);
    u32 p1 = pack_h2(t0.z * wsrc[2 * Dsz], t0.w * wsrc[3 * Dsz]);
    u32 p2 = pack_h2(t1.x * wsrc[4 * Dsz], t1.y * wsrc[5 * Dsz]);
    u32 p3 = pack_h2(t1.z * wsrc[6 * Dsz], t1.w * wsrc[7 * Dsz]);
    u32 off = (u32)(c * 8192) + (u32)(d << 7) + (((u32)s << 4) ^ ((u32)(d & 7) << 4));
    *(uint4*)(g_Wp + off) = make_uint4(p0, p1, p2, p3);
}

// ---------------- Kernel 1: token MLP via fp16 mma.sync ----------------
#define TMB 64                // tokens per block
#define KCH 64                // K per chunk
#define NCHUNK (Hsz / KCH)    // 16
// per-buffer smem: X 64x128B = 8K | W 64x128B = 8K
#define XH_OFF 0
#define WH_OFF 8192
#define BUFS   16384
#define EP_OFF (2 * BUFS)
#define WS_OFF (EP_OFF + 8 * 32 * 4)
#define SMEM_TOTAL (WS_OFF + Hsz * 4)   // 32768 + 1024 + 4096 = 37888

__global__ __launch_bounds__(256, 2) void token_mlp_mma(
    const float* __restrict__ hidden,
    const float* __restrict__ b1,
    const float* __restrict__ W2,
    const float* __restrict__ b2,
    const float* __restrict__ Ws)
{
    extern __shared__ char smem[];
    const u32 sb = smem_u32(smem);
    float* Epart = (float*)(smem + EP_OFF);
    float* WsS   = (float*)(smem + WS_OFF);

    const int tid  = threadIdx.x;
    const int w    = tid >> 5;
    const int lane = tid & 31;
    const int mb   = (w & 3) * 16;    // d tile base
    const int th   = w >> 2;          // token half (0/1), 32 tokens each

    const int gtok0 = blockIdx.x * TMB;

    // X staging ids: 4 threads per token, 16 k's each
    const int lt = tid >> 2;          // token row 0..63
    const int kq = tid & 3;           // k quarter (16 floats)
    const float* hrow = hidden + (size_t)(gtok0 + lt) * Hsz;

    // preload Ws into smem
    *(float4*)(WsS + tid * 4) = *(const float4*)(Ws + tid * 4);

    // ldmatrix lane addressing
    const int tId = lane >> 3, lr = lane & 7;
    const u32 xorv = (u32)(lr << 4);
    const u32 aRowB = (u32)((mb + lr + ((tId & 1) << 3)) << 7);
    const u32 aColB = (u32)((tId >> 1) << 4);
    const u32 bRowB = (u32)((th * 32 + lr + ((tId >> 1) << 3)) << 7);
    const u32 bColB = (u32)((tId & 1) << 4);

    float acc[4][4];
    #pragma unroll
    for (int i = 0; i < 4; i++)
        #pragma unroll
        for (int j = 0; j < 4; j++) acc[i][j] = 0.0f;
    float vpart = 0.0f;

    __syncthreads();   // WsS ready

    // ---------- staging: chunk c into buffer bi ----------
    auto stage = [&](int c, int bi) {
        char* bp = smem + bi * BUFS;
        const int k0 = c * KCH + kq * 16;
        // X: x = fp16(h); fuse V = h . Ws
        {
            float4 a0 = *(const float4*)(hrow + k0);
            float4 a1 = *(const float4*)(hrow + k0 + 4);
            float4 a2 = *(const float4*)(hrow + k0 + 8);
            float4 a3 = *(const float4*)(hrow + k0 + 12);
            float4 s0 = *(const float4*)(WsS + k0);
            float4 s1 = *(const float4*)(WsS + k0 + 4);
            float4 s2 = *(const float4*)(WsS + k0 + 8);
            float4 s3 = *(const float4*)(WsS + k0 + 12);
            vpart = fmaf(a0.x, s0.x, fmaf(a0.y, s0.y, fmaf(a0.z, s0.z, fmaf(a0.w, s0.w, vpart))));
            vpart = fmaf(a1.x, s1.x, fmaf(a1.y, s1.y, fmaf(a1.z, s1.z, fmaf(a1.w, s1.w, vpart))));
            vpart = fmaf(a2.x, s2.x, fmaf(a2.y, s2.y, fmaf(a2.z, s2.z, fmaf(a2.w, s2.w, vpart))));
            vpart = fmaf(a3.x, s3.x, fmaf(a3.y, s3.y, fmaf(a3.z, s3.z, fmaf(a3.w, s3.w, vpart))));
            u32 rb = (u32)(lt << 7);
            u32 xw = (u32)((lt & 7) << 4);
            u32 sA = (u32)(kq * 2), sB = sA + 1;
            *(uint4*)(bp + XH_OFF + rb + ((sA << 4) ^ xw)) =
                make_uint4(pack_h2(a0.x, a0.y), pack_h2(a0.z, a0.w),
                           pack_h2(a1.x, a1.y), pack_h2(a1.z, a1.w));
            *(uint4*)(bp + XH_OFF + rb + ((sB << 4) ^ xw)) =
                make_uint4(pack_h2(a2.x, a2.y), pack_h2(a2.z, a2.w),
                           pack_h2(a3.x, a3.y), pack_h2(a3.z, a3.w));
        }
        // W: linear copy of pre-swizzled chunk (512 x 16B units)
        {
            const uint4* src = (const uint4*)(g_Wp + c * 8192);
            uint4* dst = (uint4*)(bp + WH_OFF);
            dst[tid]       = src[tid];
            dst[tid + 256] = src[tid + 256];
        }
    };

    stage(0, 0);
    __syncthreads();

    for (int c = 0; c < NCHUNK; c++) {
        const int bi = c & 1;
        if (c + 1 < NCHUNK) stage(c + 1, 1 - bi);

        const u32 xh = sb + bi * BUFS + XH_OFF;
        const u32 wh = sb + bi * BUFS + WH_OFF;

        #pragma unroll
        for (int ks = 0; ks < 4; ks++) {
            const u32 kc = (u32)(ks << 5);
            u32 ah[4];
            ldsm4(ah, wh + aRowB + ((kc + aColB) ^ xorv));
            #pragma unroll
            for (int jj = 0; jj < 2; jj++) {
                const u32 rofs = bRowB + (u32)(jj << 11);
                u32 bh[4];
                ldsm4(bh, xh + rofs + ((kc + bColB) ^ xorv));
                mma_fp16(acc[2 * jj],     ah, bh[0], bh[1]);
                mma_fp16(acc[2 * jj + 1], ah, bh[2], bh[3]);
            }
        }
        __syncthreads();
    }

    // ---- V: 4 lanes per token ----
    vpart += __shfl_xor_sync(0xffffffffu, vpart, 1);
    vpart += __shfl_xor_sync(0xffffffffu, vpart, 2);
    if ((tid & 3) == 0) g_V[gtok0 + lt] = vpart;

    // ---- E partials: relu(acc + b1) . W2 over this warp's 16 d's ----
    {
        const int g = lane >> 2;
        const int d1 = mb + g, d2 = mb + 8 + g;
        const float b1a = b1[d1], b1b = b1[d2];
        const float w2a = W2[d1], w2b = W2[d2];
        #pragma unroll
        for (int j = 0; j < 4; j++) {
            float p0 = fmaxf(acc[j][0] + b1a, 0.0f) * w2a + fmaxf(acc[j][2] + b1b, 0.0f) * w2b;
            float p1 = fmaxf(acc[j][1] + b1a, 0.0f) * w2a + fmaxf(acc[j][3] + b1b, 0.0f) * w2b;
            p0 += __shfl_xor_sync(0xffffffffu, p0, 4);
            p0 += __shfl_xor_sync(0xffffffffu, p0, 8);
            p0 += __shfl_xor_sync(0xffffffffu, p0, 16);
            p1 += __shfl_xor_sync(0xffffffffu, p1, 4);
            p1 += __shfl_xor_sync(0xffffffffu, p1, 8);
            p1 += __shfl_xor_sync(0xffffffffu, p1, 16);
            if (lane < 4) {
                Epart[w * 32 + j * 8 + 2 * lane]     = p0;
                Epart[w * 32 + j * 8 + 2 * lane + 1] = p1;
            }
        }
    }
    __syncthreads();
    if (tid < TMB) {
        int half = tid >> 5, loc = tid & 31;
        float e = Epart[(half * 4 + 0) * 32 + loc] + Epart[(half * 4 + 1) * 32 + loc]
                + Epart[(half * 4 + 2) * 32 + loc] + Epart[(half * 4 + 3) * 32 + loc];
        g_E[gtok0 + tid] = e + b2[0];
    }
}

// ---------------- Kernel 2: spans, thread per (b,s,l) ----------------
#define SPB 64   // spans per block (512 threads)
__global__ __launch_bounds__(512) void span_kernel(
    const int* __restrict__ seqlen,
    const float* __restrict__ bs,
    float* __restrict__ out)
{
    __shared__ float Es[SPB + Lsz];
    __shared__ float Vs[SPB + Lsz];

    const int tid = threadIdx.x;
    const int idx0 = blockIdx.x * SPB;
    const int b = idx0 >> 9;
    const int s0 = idx0 & (Ssz - 1);
    const int len = seqlen[b];

    if (tid < SPB + Lsz) {
        int p = min(s0 + tid, Ssz - 1);
        Es[tid] = g_E[(b << 9) + p];
        Vs[tid] = g_V[(b << 9) + p];
    }
    __syncthreads();

    const int sl = tid >> 3;          // span within block
    const int l  = tid & 7;
    const int s  = s0 + sl;
    const float bsv = bs[0];

    float M = -1e30f;
    #pragma unroll
    for (int j = 0; j < Lsz; j++)
        if (j <= l && s + j < len) M = fmaxf(M, Es[sl + j]);

    float sum = 0.0f, wsum = 0.0f;
    #pragma unroll
    for (int j = 0; j < Lsz; j++)
        if (j <= l && s + j < len) {
            float p = __expf(Es[sl + j] - M);
            sum += p;
            wsum = fmaf(p, Vs[sl + j], wsum);
        }

    float score = (sum > 0.0f) ? (wsum / sum + bsv) : bsv;
    out[(size_t)(idx0 + sl) * Lsz + l] = (s < len) ? score : 0.0f;
}

extern "C" void kernel_launch(void* const* d_in, const int* in_sizes, int n_in,
                              void* d_out, int out_size)
{
    const float* hidden = (const float*)d_in[0];
    const int*   seqlen = (const int*)  d_in[1];
    const float* tw     = (const float*)d_in[2];
    const float* W1     = (const float*)d_in[3];
    const float* b1     = (const float*)d_in[4];
    const float* W2     = (const float*)d_in[5];
    const float* b2     = (const float*)d_in[6];
    const float* Ws     = (const float*)d_in[7];
    const float* bs     = (const float*)d_in[8];
    float* out = (float*)d_out;

    static bool attr_set = false;
    if (!attr_set) {
        cudaFuncSetAttribute(token_mlp_mma,
                             cudaFuncAttributeMaxDynamicSharedMemorySize, SMEM_TOTAL);
        attr_set = true;
    }

    prep_wp<<<32, 256>>>(tw, W1);
    token_mlp_mma<<<(Bsz * Ssz) / TMB, 256, SMEM_TOTAL>>>(hidden, b1, W2, b2, Ws);
    span_kernel<<<(Bsz * Ssz) / SPB, 512>>>(seqlen, bs, out);
}

// round 9
// speedup vs baseline: 2.6205x; 1.0895x over previous
#include <cuda_runtime.h>
#include <cuda_fp16.h>
#include <cstdint>

// Problem constants
#define Bsz 32
#define Ssz 512
#define Lsz 8
#define Hsz 1024
#define Dsz 64

typedef uint32_t u32;

// Scratch
__device__ float g_E[Bsz * Ssz];
__device__ float g_V[Bsz * Ssz];
// W' = diag(tw) @ W1, fp16, [chunk][d][k] in the exact swizzled smem image (16 x 8 KB)
__device__ __align__(16) char g_Wp[16 * 8192];

// ---------------- PTX wrappers (base ISA, sm_80+) ----------------
__device__ __forceinline__ u32 smem_u32(const void* p) {
    u32 a;
    asm("{ .reg .u64 t; cvta.to.shared.u64 t, %1; cvt.u32.u64 %0, t; }" : "=r"(a) : "l"(p));
    return a;
}
__device__ __forceinline__ void ldsm4(u32* r, u32 addr) {
    asm volatile("ldmatrix.sync.aligned.m8n8.x4.shared.b16 {%0,%1,%2,%3}, [%4];"
                 : "=r"(r[0]), "=r"(r[1]), "=r"(r[2]), "=r"(r[3]) : "r"(addr));
}
__device__ __forceinline__ void mma_fp16(float* c, const u32* a, u32 b0, u32 b1) {
    asm volatile("mma.sync.aligned.m16n8k16.row.col.f32.f16.f16.f32 "
                 "{%0,%1,%2,%3}, {%4,%5,%6,%7}, {%8,%9}, {%0,%1,%2,%3};"
                 : "+f"(c[0]), "+f"(c[1]), "+f"(c[2]), "+f"(c[3])
                 : "r"(a[0]), "r"(a[1]), "r"(a[2]), "r"(a[3]), "r"(b0), "r"(b1));
}
__device__ __forceinline__ u32 pack_h2(float a, float b) {
    __half2 h = __floats2half2_rn(a, b);
    return *reinterpret_cast<u32*>(&h);
}
__device__ __forceinline__ void cp_async16(u32 dst, const void* src) {
    asm volatile("cp.async.cg.shared.global [%0], [%1], 16;" :: "r"(dst), "l"(src));
}
#define CP_COMMIT() asm volatile("cp.async.commit_group;" ::: "memory")
#define CP_WAIT0()  asm volatile("cp.async.wait_group 0;" ::: "memory")

// ---------------- Kernel 0: W' = tw * W1 -> fp16, pre-swizzled (coalesced) ----------------
// 64 blocks x 128 threads; block handles k-slab [s*16, s*16+16) x all 64 d.
__global__ __launch_bounds__(128) void prep_wp(
    const float* __restrict__ tw, const float* __restrict__ W1)
{
    __shared__ float sw[16][68];
    __shared__ float twS[16];

    const int tid = threadIdx.x;
    const int s = blockIdx.x;          // slab 0..63
    const int k0 = s * 16;

    // coalesced load: 16 rows x 64 d, 8 rows per pass
    #pragma unroll
    for (int r2 = 0; r2 < 2; r2++) {
        int row = r2 * 8 + (tid >> 4);
        int c4 = (tid & 15) * 4;
        float4 v = *(const float4*)(W1 + (size_t)(k0 + row) * Dsz + c4);
        sw[row][c4]     = v.x;
        sw[row][c4 + 1] = v.y;
        sw[row][c4 + 2] = v.z;
        sw[row][c4 + 3] = v.w;
    }
    if (tid < 16) twS[tid] = tw[k0 + tid];
    __syncthreads();

    // pack: thread -> one 16B unit (8 k's of one d row)
    const int d = tid & 63;
    const int half = tid >> 6;
    const int kk = half * 8;
    u32 p[4];
    #pragma unroll
    for (int j = 0; j < 4; j++)
        p[j] = pack_h2(twS[kk + 2 * j] * sw[kk + 2 * j][d],
                       twS[kk + 2 * j + 1] * sw[kk + 2 * j + 1][d]);
    const int c = s >> 2;
    const u32 seg = (u32)((s & 3) * 2 + half);
    u32 off = (u32)(c * 8192) + (u32)(d << 7) + ((seg << 4) ^ ((u32)(d & 7) << 4));
    *(uint4*)(g_Wp + off) = make_uint4(p[0], p[1], p[2], p[3]);
}

// ---------------- Kernel 1: token MLP via fp16 mma.sync ----------------
#define TMB 64                // tokens per block
#define KCH 64                // K per chunk
#define NCHUNK (Hsz / KCH)    // 16
#define XH_OFF 0
#define WH_OFF 8192
#define BUFS   16384
#define EP_OFF (2 * BUFS)
#define WS_OFF (EP_OFF + 8 * 32 * 4)
#define SMEM_TOTAL (WS_OFF + Hsz * 4)   // 37888

__global__ __launch_bounds__(256, 2) void token_mlp_mma(
    const float* __restrict__ hidden,
    const float* __restrict__ b1,
    const float* __restrict__ W2,
    const float* __restrict__ b2,
    const float* __restrict__ Ws)
{
    extern __shared__ char smem[];
    const u32 sb = smem_u32(smem);
    float* Epart = (float*)(smem + EP_OFF);
    float* WsS   = (float*)(smem + WS_OFF);

    const int tid  = threadIdx.x;
    const int w    = tid >> 5;
    const int lane = tid & 31;
    const int mb   = (w & 3) * 16;    // d tile base
    const int th   = w >> 2;          // token half (0/1), 32 tokens each

    const int gtok0 = blockIdx.x * TMB;

    // X staging ids: 4 threads per token, 16 k's each
    const int lt = tid >> 2;          // token row 0..63
    const int kq = tid & 3;           // k quarter (16 floats)
    const float* hrow = hidden + (size_t)(gtok0 + lt) * Hsz;

    // preload Ws into smem
    *(float4*)(WsS + tid * 4) = *(const float4*)(Ws + tid * 4);

    // ldmatrix lane addressing
    const int tId = lane >> 3, lr = lane & 7;
    const u32 xorv = (u32)(lr << 4);
    const u32 aRowB = (u32)((mb + lr + ((tId & 1) << 3)) << 7);
    const u32 aColB = (u32)((tId >> 1) << 4);
    const u32 bRowB = (u32)((th * 32 + lr + ((tId >> 1) << 3)) << 7);
    const u32 bColB = (u32)((tId & 1) << 4);

    float acc[4][4];
    #pragma unroll
    for (int i = 0; i < 4; i++)
        #pragma unroll
        for (int j = 0; j < 4; j++) acc[i][j] = 0.0f;
    float vpart = 0.0f;

    __syncthreads();   // WsS ready

    // ---------- staging: chunk c into buffer bi ----------
    auto stage = [&](int c, int bi) {
        char* bp = smem + bi * BUFS;
        const int k0 = c * KCH + kq * 16;
        // X: x = fp16(h); fuse V = h . Ws
        {
            float4 a0 = *(const float4*)(hrow + k0);
            float4 a1 = *(const float4*)(hrow + k0 + 4);
            float4 a2 = *(const float4*)(hrow + k0 + 8);
            float4 a3 = *(const float4*)(hrow + k0 + 12);
            float4 s0 = *(const float4*)(WsS + k0);
            float4 s1 = *(const float4*)(WsS + k0 + 4);
            float4 s2 = *(const float4*)(WsS + k0 + 8);
            float4 s3 = *(const float4*)(WsS + k0 + 12);
            vpart = fmaf(a0.x, s0.x, fmaf(a0.y, s0.y, fmaf(a0.z, s0.z, fmaf(a0.w, s0.w, vpart))));
            vpart = fmaf(a1.x, s1.x, fmaf(a1.y, s1.y, fmaf(a1.z, s1.z, fmaf(a1.w, s1.w, vpart))));
            vpart = fmaf(a2.x, s2.x, fmaf(a2.y, s2.y, fmaf(a2.z, s2.z, fmaf(a2.w, s2.w, vpart))));
            vpart = fmaf(a3.x, s3.x, fmaf(a3.y, s3.y, fmaf(a3.z, s3.z, fmaf(a3.w, s3.w, vpart))));
            u32 rb = (u32)(lt << 7);
            u32 xw = (u32)((lt & 7) << 4);
            u32 sA = (u32)(kq * 2), sB = sA + 1;
            *(uint4*)(bp + XH_OFF + rb + ((sA << 4) ^ xw)) =
                make_uint4(pack_h2(a0.x, a0.y), pack_h2(a0.z, a0.w),
                           pack_h2(a1.x, a1.y), pack_h2(a1.z, a1.w));
            *(uint4*)(bp + XH_OFF + rb + ((sB << 4) ^ xw)) =
                make_uint4(pack_h2(a2.x, a2.y), pack_h2(a2.z, a2.w),
                           pack_h2(a3.x, a3.y), pack_h2(a3.z, a3.w));
        }
        // W: async copy of pre-swizzled chunk (512 x 16B units)
        {
            const char* src = g_Wp + c * 8192;
            u32 dst = sb + bi * BUFS + WH_OFF;
            cp_async16(dst + tid * 16,         src + tid * 16);
            cp_async16(dst + (tid + 256) * 16, src + (tid + 256) * 16);
            CP_COMMIT();
        }
    };

    stage(0, 0);
    CP_WAIT0();
    __syncthreads();

    for (int c = 0; c < NCHUNK; c++) {
        const int bi = c & 1;
        if (c + 1 < NCHUNK) stage(c + 1, 1 - bi);

        const u32 xh = sb + bi * BUFS + XH_OFF;
        const u32 wh = sb + bi * BUFS + WH_OFF;

        // batch all A-fragment ldsm (independent)
        u32 ah[4][4];
        #pragma unroll
        for (int ks = 0; ks < 4; ks++)
            ldsm4(ah[ks], wh + aRowB + (((u32)(ks << 5) + aColB) ^ xorv));

        #pragma unroll
        for (int ks = 0; ks < 4; ks++) {
            const u32 kc = (u32)(ks << 5);
            u32 b0[4], b1r[4];
            ldsm4(b0,  xh + bRowB + ((kc + bColB) ^ xorv));
            ldsm4(b1r, xh + bRowB + 2048 + ((kc + bColB) ^ xorv));
            mma_fp16(acc[0], ah[ks], b0[0], b0[1]);
            mma_fp16(acc[1], ah[ks], b0[2], b0[3]);
            mma_fp16(acc[2], ah[ks], b1r[0], b1r[1]);
            mma_fp16(acc[3], ah[ks], b1r[2], b1r[3]);
        }
        CP_WAIT0();
        __syncthreads();
    }

    // ---- V: 4 lanes per token ----
    vpart += __shfl_xor_sync(0xffffffffu, vpart, 1);
    vpart += __shfl_xor_sync(0xffffffffu, vpart, 2);
    if ((tid & 3) == 0) g_V[gtok0 + lt] = vpart;

    // ---- E partials: relu(acc + b1) . W2 over this warp's 16 d's ----
    {
        const int g = lane >> 2;
        const int d1 = mb + g, d2 = mb + 8 + g;
        const float b1a = b1[d1], b1b = b1[d2];
        const float w2a = W2[d1], w2b = W2[d2];
        #pragma unroll
        for (int j = 0; j < 4; j++) {
            float p0 = fmaxf(acc[j][0] + b1a, 0.0f) * w2a + fmaxf(acc[j][2] + b1b, 0.0f) * w2b;
            float p1 = fmaxf(acc[j][1] + b1a, 0.0f) * w2a + fmaxf(acc[j][3] + b1b, 0.0f) * w2b;
            p0 += __shfl_xor_sync(0xffffffffu, p0, 4);
            p0 += __shfl_xor_sync(0xffffffffu, p0, 8);
            p0 += __shfl_xor_sync(0xffffffffu, p0, 16);
            p1 += __shfl_xor_sync(0xffffffffu, p1, 4);
            p1 += __shfl_xor_sync(0xffffffffu, p1, 8);
            p1 += __shfl_xor_sync(0xffffffffu, p1, 16);
            if (lane < 4) {
                Epart[w * 32 + j * 8 + 2 * lane]     = p0;
                Epart[w * 32 + j * 8 + 2 * lane + 1] = p1;
            }
        }
    }
    __syncthreads();
    if (tid < TMB) {
        int half = tid >> 5, loc = tid & 31;
        float e = Epart[(half * 4 + 0) * 32 + loc] + Epart[(half * 4 + 1) * 32 + loc]
                + Epart[(half * 4 + 2) * 32 + loc] + Epart[(half * 4 + 3) * 32 + loc];
        g_E[gtok0 + tid] = e + b2[0];
    }
}

// ---------------- Kernel 2: spans, thread per (b,s,l) ----------------
#define SPB 64   // spans per block (512 threads)
__global__ __launch_bounds__(512) void span_kernel(
    const int* __restrict__ seqlen,
    const float* __restrict__ bs,
    float* __restrict__ out)
{
    __shared__ float Es[SPB + Lsz];
    __shared__ float Vs[SPB + Lsz];

    const int tid = threadIdx.x;
    const int idx0 = blockIdx.x * SPB;
    const int b = idx0 >> 9;
    const int s0 = idx0 & (Ssz - 1);
    const int len = seqlen[b];

    if (tid < SPB + Lsz) {
        int p = min(s0 + tid, Ssz - 1);
        Es[tid] = g_E[(b << 9) + p];
        Vs[tid] = g_V[(b << 9) + p];
    }
    __syncthreads();

    const int sl = tid >> 3;          // span within block
    const int l  = tid & 7;
    const int s  = s0 + sl;
    const float bsv = bs[0];

    float M = -1e30f;
    #pragma unroll
    for (int j = 0; j < Lsz; j++)
        if (j <= l && s + j < len) M = fmaxf(M, Es[sl + j]);

    float sum = 0.0f, wsum = 0.0f;
    #pragma unroll
    for (int j = 0; j < Lsz; j++)
        if (j <= l && s + j < len) {
            float p = __expf(Es[sl + j] - M);
            sum += p;
            wsum = fmaf(p, Vs[sl + j], wsum);
        }

    float score = (sum > 0.0f) ? (wsum / sum + bsv) : bsv;
    out[(size_t)(idx0 + sl) * Lsz + l] = (s < len) ? score : 0.0f;
}

extern "C" void kernel_launch(void* const* d_in, const int* in_sizes, int n_in,
                              void* d_out, int out_size)
{
    const float* hidden = (const float*)d_in[0];
    const int*   seqlen = (const int*)  d_in[1];
    const float* tw     = (const float*)d_in[2];
    const float* W1     = (const float*)d_in[3];
    const float* b1     = (const float*)d_in[4];
    const float* W2     = (const float*)d_in[5];
    const float* b2     = (const float*)d_in[6];
    const float* Ws     = (const float*)d_in[7];
    const float* bs     = (const float*)d_in[8];
    float* out = (float*)d_out;

    static bool attr_set = false;
    if (!attr_set) {
        cudaFuncSetAttribute(token_mlp_mma,
                             cudaFuncAttributeMaxDynamicSharedMemorySize, SMEM_TOTAL);
        attr_set = true;
    }

    prep_wp<<<64, 128>>>(tw, W1);
    token_mlp_mma<<<(Bsz * Ssz) / TMB, 256, SMEM_TOTAL>>>(hidden, b1, W2, b2, Ws);
    span_kernel<<<(Bsz * Ssz) / SPB, 512>>>(seqlen, bs, out);
}